// round 5
// baseline (speedup 1.0000x reference)
#include <cuda_runtime.h>
#include <cuda_fp16.h>
#include <stdint.h>

// Problem dims
#define BB   64
#define TT   4096
#define NTOK (BB*TT)          // 262144
#define TOKPC 256             // tokens per CTA
#define NCTAS (NTOK/TOKPC)    // 1024

// smem strides (halves), conflict-free (row stride mod 128B cycles all banks)
#define SC 104                // comb stride (K=96 padded), 208B row
#define SH 136                // hidden/weight stride (K=128 padded), 272B row

// ---------------- device scratch ----------------
__device__ __align__(16) __half g_wT[(size_t)BB * 64 * 64 * 64]; // [b][y][x][c] fp16, 32MB
__device__ __align__(16) __half g_wts[4 * 4 * 128 * 128];        // [net][layer][n][k] fp16
__device__ float g_bias[4 * 4 * 128];                            // [net][layer][n]
__device__ float g_part[2][NCTAS];                               // per-tile s-sums

// ---------------- helpers ----------------
__device__ __forceinline__ void mma16816(float c[4], const unsigned a[4],
                                         unsigned b0, unsigned b1) {
    asm volatile(
        "mma.sync.aligned.m16n8k16.row.col.f32.f16.f16.f32 "
        "{%0,%1,%2,%3}, {%4,%5,%6,%7}, {%8,%9}, {%0,%1,%2,%3};"
        : "+f"(c[0]), "+f"(c[1]), "+f"(c[2]), "+f"(c[3])
        : "r"(a[0]), "r"(a[1]), "r"(a[2]), "r"(a[3]), "r"(b0), "r"(b1));
}

__device__ __forceinline__ void ldsm_x4(unsigned r[4], uint32_t addr) {
    asm volatile("ldmatrix.sync.aligned.m8n8.x4.shared.b16 {%0,%1,%2,%3}, [%4];"
                 : "=r"(r[0]), "=r"(r[1]), "=r"(r[2]), "=r"(r[3]) : "r"(addr));
}

__device__ __forceinline__ uint32_t smem_u32(const void* p) {
    uint32_t a;
    asm("{ .reg .u64 t; cvta.to.shared.u64 t, %1; cvt.u32.u64 %0, t; }" : "=r"(a) : "l"(p));
    return a;
}

// silu with single MUFU: v * 0.5*(tanh(v/2)+1)
__device__ __forceinline__ float fast_silu(float v) {
    float t;
    asm("tanh.approx.f32 %0, %1;" : "=f"(t) : "f"(0.5f * v));
    return 0.5f * v * (t + 1.0f);
}

// ---------------- transpose w[B,C,H,W] f32 -> wT[b][y][x][c] fp16 ----------------
__global__ void k_transpose(const float* __restrict__ w) {
    __shared__ float tile[64][65];
    int bid = blockIdx.x;              // 4096 blocks = (b, y)
    int b = bid >> 6, y = bid & 63;
    int t = threadIdx.x;
    {
        int c = t >> 2, xq = (t & 3) * 16;
        const float4* src = (const float4*)(w + ((((b << 6) | c) << 6 | y) << 6) + xq);
#pragma unroll
        for (int j = 0; j < 4; j++) {
            float4 v = src[j];
            tile[c][xq + 4 * j + 0] = v.x;
            tile[c][xq + 4 * j + 1] = v.y;
            tile[c][xq + 4 * j + 2] = v.z;
            tile[c][xq + 4 * j + 3] = v.w;
        }
    }
    __syncthreads();
    {
        int xx = t >> 2, cq = (t & 3) * 16;
        __half2* dst = (__half2*)(g_wT + ((((size_t)(((b << 6) | y)) << 6 | xx)) << 6) + cq);
#pragma unroll
        for (int j = 0; j < 8; j++)
            dst[j] = __floats2half2_rn(tile[cq + 2 * j][xx], tile[cq + 2 * j + 1][xx]);
    }
}

// ---------------- pack weights (permuted cols: [lf 0..63 | cond 64..79 | z 80 | 0]) ----------------
__global__ void k_pack(const float* __restrict__ W0, const float* __restrict__ b0,
                       const float* __restrict__ W1, const float* __restrict__ b1) {
    int idx = blockIdx.x * 256 + threadIdx.x;      // 262144 total
    int net = idx >> 16;
    int rem = idx & 65535;
    int layer = rem >> 14;
    int rem2 = rem & 16383;
    int n = rem2 >> 7, k = rem2 & 127;
    float v = 0.f;
    if (layer == 0) {
        int oc = -1;
        if (k < 64) oc = 1 + k;                    // lf -> orig cols 1..64
        else if (k < 80) oc = 65 + (k - 64);       // cond -> orig cols 65..80
        else if (k == 80) oc = 0;                  // z_keep -> orig col 0
        if (oc >= 0) v = W0[(net * 128 + n) * 81 + oc];
    } else {
        v = W1[((net * 3 + (layer - 1)) * 128 + n) * 128 + k];
    }
    g_wts[idx] = __float2half_rn(v);
    if (idx < 2048) {
        int bn = idx >> 9, bl = (idx >> 7) & 3, bb_ = idx & 127;
        g_bias[idx] = (bl == 0) ? b0[bn * 128 + bb_]
                                : b1[((bn * 3 + bl - 1) * 128) + bb_];
    }
}

// ---------------- fused coupling pass ----------------
template <int PASS>
__global__ void __launch_bounds__(256, 1) k_pass(
    const float* __restrict__ x, const float* __restrict__ cond,
    const float* __restrict__ W2, const float* __restrict__ b2,
    float* __restrict__ out) {
    extern __shared__ __align__(16) char smraw[];
    __half* combS = (__half*)smraw;                       // 256 x SC
    __half* hS    = (__half*)(smraw + 53248);             // 256 x SH (in-place hidden)
    __half* wS    = (__half*)(smraw + 122880);            // 128 x SH (weights)
    float*  fb    = (float*)(smraw + 157696);
    float*  sbias = fb;            // 128
    float*  w2s   = fb + 128;      // 128
    float*  sraw  = fb + 256;      // 256
    float*  traw  = fb + 512;      // 256
    float*  spart = fb + 768;      // 512 (2 col-groups x 256 rows)
    float*  sred  = fb + 1280;     // 256

    int tid = threadIdx.x;
    int tile = blockIdx.x;

    // ===== gather + build comb (one thread per token) =====
    {
        int g0 = tile * TOKPC + tid;
        int b = g0 >> 12;
        float zy = __ldg(&x[g0 * 2 + 1]);
        float zx = (PASS == 0) ? __ldg(&x[g0 * 2]) : out[g0 * 2];
        float zkeep = (PASS == 0) ? zy : zx;
        float ix = zx * 63.f, iy = zy * 63.f;
        float ix0 = floorf(ix), iy0 = floorf(iy);
        float wx1 = ix - ix0, wx0 = 1.f - wx1;
        float wy1 = iy - iy0, wy0 = 1.f - wy1;
        float acc[64];
#pragma unroll
        for (int i = 0; i < 64; i++) acc[i] = 0.f;
        float cxs[4] = {ix0, ix0 + 1.f, ix0, ix0 + 1.f};
        float cys[4] = {iy0, iy0, iy0 + 1.f, iy0 + 1.f};
        float cws[4] = {wy0 * wx0, wy0 * wx1, wy1 * wx0, wy1 * wx1};
#pragma unroll
        for (int cr = 0; cr < 4; cr++) {
            float xf = cxs[cr], yf = cys[cr], wt = cws[cr];
            if (xf >= 0.f && xf <= 63.f && yf >= 0.f && yf <= 63.f) {
                int xi = (int)xf, yi = (int)yf;
                const __half2* src = (const __half2*)(
                    g_wT + (((size_t)((b << 6) | yi) << 6 | xi) << 6));
#pragma unroll
                for (int j = 0; j < 32; j++) {
                    float2 f = __half22float2(src[j]);
                    acc[2 * j]     += wt * f.x;
                    acc[2 * j + 1] += wt * f.y;
                }
            }
        }
        __half* crow = combS + tid * SC;
        __half2* dst = (__half2*)crow;
#pragma unroll
        for (int j = 0; j < 32; j++) dst[j] = __floats2half2_rn(acc[2 * j], acc[2 * j + 1]);
#pragma unroll
        for (int i = 0; i < 16; i++)
            crow[64 + i] = __float2half_rn(__ldg(&cond[b * 16 + i]));
        crow[80] = __float2half_rn(zkeep);
#pragma unroll
        for (int cc = 81; cc < 96; cc++) crow[cc] = __float2half_rn(0.f);
    }

    int wid = tid >> 5, lane = tid & 31;
    int gid = lane >> 2, tig = lane & 3;
    int warpM = (wid & 3) * 64;          // 4 M-groups of 64 rows
    int warpN = (wid >> 2) * 64;         // 2 N-groups of 64 cols
    int cgrp  = wid >> 2;

    // ldmatrix per-thread offsets
    int aRow = lane & 15;
    int aK   = (lane >> 4) * 8;
    int bRow = (lane & 7) + ((lane >> 4) & 1) * 8;
    int bK   = ((lane >> 3) & 1) * 8;

    uint32_t combA = smem_u32(combS);
    uint32_t hA    = smem_u32(hS);
    uint32_t wA    = smem_u32(wS);

    // ===== two MLPs (s-net then t-net) =====
    for (int ni = 0; ni < 2; ni++) {
        int net = PASS * 2 + ni;
        for (int layer = 0; layer < 4; layer++) {
            // stage weights + bias into smem
            const int4* gw = (const int4*)(g_wts + ((net * 4 + layer) << 14));
#pragma unroll
            for (int i = 0; i < 8; i++) {
                int ci = tid + i * 256;                 // 0..2047
                int n = ci >> 4, q = ci & 15;
                *(int4*)(wS + n * SH + q * 8) = gw[ci];
            }
            if (tid < 128) {
                sbias[tid] = g_bias[(net * 4 + layer) * 128 + tid];
                if (layer == 3) w2s[tid] = __ldg(&W2[net * 128 + tid]);
            }
            __syncthreads();

            uint32_t Aaddr = (layer == 0) ? combA : hA;
            int sa = (layer == 0) ? SC : SH;
            int ksteps = (layer == 0) ? 6 : 8;

            uint32_t abase[4];
#pragma unroll
            for (int mt = 0; mt < 4; mt++)
                abase[mt] = Aaddr + ((warpM + mt * 16 + aRow) * sa + aK) * 2;
            uint32_t bb = wA + ((warpN + bRow) * SH + bK) * 2;

            float acc[4][8][4];
#pragma unroll
            for (int mt = 0; mt < 4; mt++)
#pragma unroll
                for (int nt = 0; nt < 8; nt++)
#pragma unroll
                    for (int q = 0; q < 4; q++) acc[mt][nt][q] = 0.f;

            for (int ks = 0; ks < ksteps; ks++) {
                unsigned af[4][4];
#pragma unroll
                for (int mt = 0; mt < 4; mt++) ldsm_x4(af[mt], abase[mt] + ks * 32);
#pragma unroll
                for (int ntp = 0; ntp < 4; ntp++) {
                    unsigned bf[4];
                    ldsm_x4(bf, bb + (ntp * 16 * SH) * 2 + ks * 32);
#pragma unroll
                    for (int mt = 0; mt < 4; mt++) {
                        mma16816(acc[mt][2 * ntp],     af[mt], bf[0], bf[1]);
                        mma16816(acc[mt][2 * ntp + 1], af[mt], bf[2], bf[3]);
                    }
                }
            }
            __syncthreads();   // all reads of A/W done before in-place writes

            if (layer < 3) {
                // epilogue: bias + silu -> hS (fp16, in-place)
#pragma unroll
                for (int mt = 0; mt < 4; mt++) {
#pragma unroll
                    for (int nt = 0; nt < 8; nt++) {
                        int r = warpM + mt * 16 + gid;
                        int c = warpN + nt * 8 + tig * 2;
                        float b0v = sbias[c], b1v = sbias[c + 1];
                        float v0 = fast_silu(acc[mt][nt][0] + b0v);
                        float v1 = fast_silu(acc[mt][nt][1] + b1v);
                        float v2 = fast_silu(acc[mt][nt][2] + b0v);
                        float v3 = fast_silu(acc[mt][nt][3] + b1v);
                        *(__half2*)(hS + r * SH + c)       = __floats2half2_rn(v0, v1);
                        *(__half2*)(hS + (r + 8) * SH + c) = __floats2half2_rn(v2, v3);
                    }
                }
            } else {
                // fused GEMV: silu then dot with W2 over this warp's 64 cols
                float w2v0[8], w2v1[8], bv0[8], bv1[8];
#pragma unroll
                for (int nt = 0; nt < 8; nt++) {
                    int c = warpN + nt * 8 + tig * 2;
                    w2v0[nt] = w2s[c]; w2v1[nt] = w2s[c + 1];
                    bv0[nt] = sbias[c]; bv1[nt] = sbias[c + 1];
                }
#pragma unroll
                for (int mt = 0; mt < 4; mt++) {
                    float p0 = 0.f, p1 = 0.f;
#pragma unroll
                    for (int nt = 0; nt < 8; nt++) {
                        p0 += fast_silu(acc[mt][nt][0] + bv0[nt]) * w2v0[nt]
                            + fast_silu(acc[mt][nt][1] + bv1[nt]) * w2v1[nt];
                        p1 += fast_silu(acc[mt][nt][2] + bv0[nt]) * w2v0[nt]
                            + fast_silu(acc[mt][nt][3] + bv1[nt]) * w2v1[nt];
                    }
                    p0 += __shfl_xor_sync(0xffffffffu, p0, 1);
                    p0 += __shfl_xor_sync(0xffffffffu, p0, 2);
                    p1 += __shfl_xor_sync(0xffffffffu, p1, 1);
                    p1 += __shfl_xor_sync(0xffffffffu, p1, 2);
                    if (tig == 0) {
                        spart[cgrp * 256 + warpM + mt * 16 + gid]     = p0;
                        spart[cgrp * 256 + warpM + mt * 16 + gid + 8] = p1;
                    }
                }
            }
        }
        __syncthreads();
        {
            float r = spart[tid] + spart[256 + tid] + __ldg(&b2[net]);
            if (ni == 0) sraw[tid] = r; else traw[tid] = r;
        }
        __syncthreads();
    }

    // ===== coupling epilogue + deterministic block reduce of s =====
    {
        int g0 = tile * TOKPC + tid;
        float zold = (PASS == 0) ? __ldg(&x[g0 * 2]) : __ldg(&x[g0 * 2 + 1]);
        float sv = tanhf(sraw[tid]) * 1.5f;
        float z = zold * __expf(sv) + traw[tid];
        out[g0 * 2 + PASS] = z;
        sred[tid] = sv;
    }
    __syncthreads();
    if (tid < 128) sred[tid] += sred[tid + 128];
    __syncthreads();
    if (tid < 64) sred[tid] += sred[tid + 64];
    __syncthreads();
    if (tid < 32) {
        float v = sred[tid] + sred[tid + 32];
#pragma unroll
        for (int off = 16; off; off >>= 1) v += __shfl_xor_sync(0xffffffffu, v, off);
        if (tid == 0) g_part[PASS][tile] = v;
    }
}

// ---------------- log-det reduce ----------------
__global__ void k_reduce(float* __restrict__ out) {
    int b = threadIdx.x;
    if (b < BB) {
        float acc = 0.f;
        for (int i = 0; i < 16; i++)
            acc += g_part[0][b * 16 + i] + g_part[1][b * 16 + i];
        out[(size_t)NTOK * 2 + b] = acc;
    }
}

// ---------------- launcher ----------------
extern "C" void kernel_launch(void* const* d_in, const int* in_sizes, int n_in,
                              void* d_out, int out_size) {
    const float* x    = (const float*)d_in[0];
    const float* w    = (const float*)d_in[1];
    const float* cond = (const float*)d_in[2];
    const float* W0   = (const float*)d_in[3];
    const float* b0   = (const float*)d_in[4];
    const float* W1   = (const float*)d_in[5];
    const float* b1   = (const float*)d_in[6];
    const float* W2   = (const float*)d_in[7];
    const float* b2   = (const float*)d_in[8];
    float* out = (float*)d_out;

    const int SMEM = 53248 + 69632 + 34816 + 1536 * 4;  // 163840
    cudaFuncSetAttribute(k_pass<0>, cudaFuncAttributeMaxDynamicSharedMemorySize, SMEM);
    cudaFuncSetAttribute(k_pass<1>, cudaFuncAttributeMaxDynamicSharedMemorySize, SMEM);

    k_transpose<<<4096, 256>>>(w);
    k_pack<<<1024, 256>>>(W0, b0, W1, b1);
    k_pass<0><<<NCTAS, 256, SMEM>>>(x, cond, W2, b2, out);
    k_pass<1><<<NCTAS, 256, SMEM>>>(x, cond, W2, b2, out);
    k_reduce<<<1, 64>>>(out);
}

// round 6
// speedup vs baseline: 1.2143x; 1.2143x over previous
#include <cuda_runtime.h>
#include <cuda_fp16.h>
#include <stdint.h>

// Problem dims
#define BB   64
#define TT   4096
#define NTOK (BB*TT)          // 262144
#define TOKPC 256             // tokens per CTA
#define NCTAS (NTOK/TOKPC)    // 1024

// smem strides (halves), conflict-free for LDSM (row stride in 16B units coprime with 8)
#define SC 104                // comb stride (K=96 padded): 208B, 13*16B -> coprime 8
#define SH 136                // weight stride (K=128 padded): 272B, 17*16B -> coprime 8

// ---------------- device scratch ----------------
__device__ __align__(16) __half g_wT[(size_t)BB * 64 * 64 * 64]; // [b][y][x][c] fp16, 32MB
__device__ __align__(16) __half g_wts[4 * 4 * 128 * 128];        // [net][layer][n][k] fp16
__device__ float g_bias[4 * 4 * 128];                            // [net][layer][n]
__device__ float g_part[2][NCTAS];                               // per-tile s-sums

// ---------------- helpers ----------------
__device__ __forceinline__ void mma16816(float c[4], const unsigned a0, const unsigned a1,
                                         const unsigned a2, const unsigned a3,
                                         unsigned b0, unsigned b1) {
    asm volatile(
        "mma.sync.aligned.m16n8k16.row.col.f32.f16.f16.f32 "
        "{%0,%1,%2,%3}, {%4,%5,%6,%7}, {%8,%9}, {%0,%1,%2,%3};"
        : "+f"(c[0]), "+f"(c[1]), "+f"(c[2]), "+f"(c[3])
        : "r"(a0), "r"(a1), "r"(a2), "r"(a3), "r"(b0), "r"(b1));
}

__device__ __forceinline__ void ldsm_x4(unsigned r[4], uint32_t addr) {
    asm volatile("ldmatrix.sync.aligned.m8n8.x4.shared.b16 {%0,%1,%2,%3}, [%4];"
                 : "=r"(r[0]), "=r"(r[1]), "=r"(r[2]), "=r"(r[3]) : "r"(addr));
}

__device__ __forceinline__ uint32_t smem_u32(const void* p) {
    uint32_t a;
    asm("{ .reg .u64 t; cvta.to.shared.u64 t, %1; cvt.u32.u64 %0, t; }" : "=r"(a) : "l"(p));
    return a;
}

__device__ __forceinline__ float fast_silu(float v) {
    float t;
    asm("tanh.approx.f32 %0, %1;" : "=f"(t) : "f"(0.5f * v));
    return 0.5f * v * (t + 1.0f);
}

__device__ __forceinline__ unsigned packh2(float a, float b) {
    __half2 h = __floats2half2_rn(a, b);
    return *(unsigned*)&h;
}

#define CP_ASYNC16(dst, src) \
    asm volatile("cp.async.cg.shared.global [%0], [%1], 16;" :: "r"(dst), "l"(src))
#define CP_COMMIT() asm volatile("cp.async.commit_group;" ::: "memory")

// ---------------- transpose w[B,C,H,W] f32 -> wT[b][y][x][c] fp16 ----------------
__global__ void k_transpose(const float* __restrict__ w) {
    __shared__ float tile[64][65];
    int bid = blockIdx.x;
    int b = bid >> 6, y = bid & 63;
    int t = threadIdx.x;
    {
        int c = t >> 2, xq = (t & 3) * 16;
        const float4* src = (const float4*)(w + ((((b << 6) | c) << 6 | y) << 6) + xq);
#pragma unroll
        for (int j = 0; j < 4; j++) {
            float4 v = src[j];
            tile[c][xq + 4 * j + 0] = v.x;
            tile[c][xq + 4 * j + 1] = v.y;
            tile[c][xq + 4 * j + 2] = v.z;
            tile[c][xq + 4 * j + 3] = v.w;
        }
    }
    __syncthreads();
    {
        int xx = t >> 2, cq = (t & 3) * 16;
        __half2* dst = (__half2*)(g_wT + ((((size_t)(((b << 6) | y)) << 6 | xx)) << 6) + cq);
#pragma unroll
        for (int j = 0; j < 8; j++)
            dst[j] = __floats2half2_rn(tile[cq + 2 * j][xx], tile[cq + 2 * j + 1][xx]);
    }
}

// ---------------- pack weights (permuted cols: [lf 0..63 | cond 64..79 | z 80 | 0]) ----------------
__global__ void k_pack(const float* __restrict__ W0, const float* __restrict__ b0,
                       const float* __restrict__ W1, const float* __restrict__ b1) {
    int idx = blockIdx.x * 256 + threadIdx.x;      // 262144 total
    int net = idx >> 16;
    int rem = idx & 65535;
    int layer = rem >> 14;
    int rem2 = rem & 16383;
    int n = rem2 >> 7, k = rem2 & 127;
    float v = 0.f;
    if (layer == 0) {
        int oc = -1;
        if (k < 64) oc = 1 + k;
        else if (k < 80) oc = 65 + (k - 64);
        else if (k == 80) oc = 0;
        if (oc >= 0) v = W0[(net * 128 + n) * 81 + oc];
    } else {
        v = W1[((net * 3 + (layer - 1)) * 128 + n) * 128 + k];
    }
    g_wts[idx] = __float2half_rn(v);
    if (idx < 2048) {
        int bn = idx >> 9, bl = (idx >> 7) & 3, bb_ = idx & 127;
        g_bias[idx] = (bl == 0) ? b0[bn * 128 + bb_]
                                : b1[((bn * 3 + bl - 1) * 128) + bb_];
    }
}

// ---------------- fused coupling pass: A-in-registers pipeline ----------------
template <int PASS>
__global__ void __launch_bounds__(256, 1) k_pass(
    const float* __restrict__ x, const float* __restrict__ cond,
    const float* __restrict__ W2, const float* __restrict__ b2,
    float* __restrict__ out) {
    extern __shared__ __align__(16) char smraw[];
    __half* combS = (__half*)smraw;                          // 256 x SC
    __half* wbuf0 = (__half*)(smraw + 53248);                // 3 weight buffers 128 x SH
    float*  sbias = (float*)(smraw + 157696);                // 8 x 128
    float*  w2s   = (float*)(smraw + 161792);                // 2 x 128
    float*  sraw  = (float*)(smraw + 162816);                // 256
    float*  traw  = (float*)(smraw + 163840);                // 256
    float*  sred  = (float*)(smraw + 164864);                // 256

    int tid = threadIdx.x;
    int wid = tid >> 5, lane = tid & 31;
    int gid = lane >> 2, tig = lane & 3;
    int tile = blockIdx.x;

    uint32_t combA = smem_u32(combS);
    uint32_t wbA[3] = {smem_u32(wbuf0), smem_u32(wbuf0 + 128 * SH),
                       smem_u32(wbuf0 + 2 * 128 * SH)};

    // stage biases + w2 (contiguous per pass)
#pragma unroll
    for (int j = 0; j < 4; j++)
        sbias[tid + j * 256] = g_bias[PASS * 1024 + tid + j * 256];
    w2s[tid & 255] = __ldg(&W2[PASS * 256 + tid]);

    // prologue weight prefetch: layers 0 and 1
    {
#pragma unroll
        for (int i = 0; i < 8; i++) {
            int ci = tid + i * 256;
            int n = ci >> 4, q = ci & 15;
            CP_ASYNC16(wbA[0] + (n * SH + q * 8) * 2,
                       (const char*)g_wts + ((size_t)(PASS * 8 + 0) << 15) + ci * 16);
        }
        CP_COMMIT();
#pragma unroll
        for (int i = 0; i < 8; i++) {
            int ci = tid + i * 256;
            int n = ci >> 4, q = ci & 15;
            CP_ASYNC16(wbA[1] + (n * SH + q * 8) * 2,
                       (const char*)g_wts + ((size_t)(PASS * 8 + 1) << 15) + ci * 16);
        }
        CP_COMMIT();
    }

    // ===== gather + build comb (one thread per token) =====
    {
        int g0 = tile * TOKPC + tid;
        int b = g0 >> 12;
        float zy = __ldg(&x[g0 * 2 + 1]);
        float zx = (PASS == 0) ? __ldg(&x[g0 * 2]) : out[g0 * 2];
        float zkeep = (PASS == 0) ? zy : zx;
        float ix = zx * 63.f, iy = zy * 63.f;
        float ix0 = floorf(ix), iy0 = floorf(iy);
        float wx1 = ix - ix0, wx0 = 1.f - wx1;
        float wy1 = iy - iy0, wy0 = 1.f - wy1;
        float acc[64];
#pragma unroll
        for (int i = 0; i < 64; i++) acc[i] = 0.f;
        float cxs[4] = {ix0, ix0 + 1.f, ix0, ix0 + 1.f};
        float cys[4] = {iy0, iy0, iy0 + 1.f, iy0 + 1.f};
        float cws[4] = {wy0 * wx0, wy0 * wx1, wy1 * wx0, wy1 * wx1};
#pragma unroll
        for (int cr = 0; cr < 4; cr++) {
            float xf = cxs[cr], yf = cys[cr], wt = cws[cr];
            if (xf >= 0.f && xf <= 63.f && yf >= 0.f && yf <= 63.f) {
                int xi = (int)xf, yi = (int)yf;
                const __half2* src = (const __half2*)(
                    g_wT + (((size_t)((b << 6) | yi) << 6 | xi) << 6));
#pragma unroll
                for (int j = 0; j < 32; j++) {
                    float2 f = __half22float2(src[j]);
                    acc[2 * j]     += wt * f.x;
                    acc[2 * j + 1] += wt * f.y;
                }
            }
        }
        __half* crow = combS + tid * SC;
        __half2* dst = (__half2*)crow;
#pragma unroll
        for (int j = 0; j < 32; j++) dst[j] = __floats2half2_rn(acc[2 * j], acc[2 * j + 1]);
#pragma unroll
        for (int i = 0; i < 16; i++)
            crow[64 + i] = __float2half_rn(__ldg(&cond[b * 16 + i]));
        crow[80] = __float2half_rn(zkeep);
#pragma unroll
        for (int cc = 81; cc < 96; cc++) crow[cc] = __float2half_rn(0.f);
    }

    // ldmatrix per-thread offsets
    int aRow = lane & 15;
    int aK   = (lane >> 4) * 8;
    int bRow = (lane & 7) + ((lane >> 4) & 1) * 8;
    int bK   = ((lane >> 3) & 1) * 8;

    unsigned aPack[2][16][2];   // half2-packed activations: [m-tile][n-tile][row/row+8]

    // ===== 8 layers (2 nets x 4), weights pipelined via cp.async =====
    for (int li = 0; li < 8; li++) {
        if (li < 7) asm volatile("cp.async.wait_group 1;" ::: "memory");
        else        asm volatile("cp.async.wait_group 0;" ::: "memory");
        __syncthreads();

        // prefetch layer li+2 into buf[(li+2)%3] (that buffer is fully consumed)
        if (li + 2 < 8) {
            uint32_t dstA = wbA[(li + 2) % 3];
            const char* srcp = (const char*)g_wts + ((size_t)(PASS * 8 + li + 2) << 15);
#pragma unroll
            for (int i = 0; i < 8; i++) {
                int ci = tid + i * 256;
                int n = ci >> 4, q = ci & 15;
                CP_ASYNC16(dstA + (n * SH + q * 8) * 2, srcp + ci * 16);
            }
            CP_COMMIT();
        }

        uint32_t wA = wbA[li % 3];
        uint32_t bb = wA + (bRow * SH + bK) * 2;
        int layer = li & 3;

        float acc[2][16][4];
#pragma unroll
        for (int mt = 0; mt < 2; mt++)
#pragma unroll
            for (int nt = 0; nt < 16; nt++)
#pragma unroll
                for (int q = 0; q < 4; q++) acc[mt][nt][q] = 0.f;

        if (layer == 0) {
            // A from comb via LDSM, K=96 (6 ksteps)
            uint32_t a0 = combA + ((wid * 32 + aRow) * SC + aK) * 2;
            uint32_t a1 = combA + ((wid * 32 + 16 + aRow) * SC + aK) * 2;
#pragma unroll
            for (int ks = 0; ks < 6; ks++) {
                unsigned af0[4], af1[4];
                ldsm_x4(af0, a0 + ks * 32);
                ldsm_x4(af1, a1 + ks * 32);
#pragma unroll
                for (int ntp = 0; ntp < 8; ntp++) {
                    unsigned bf[4];
                    ldsm_x4(bf, bb + (ntp * 16 * SH) * 2 + ks * 32);
                    mma16816(acc[0][2 * ntp],     af0[0], af0[1], af0[2], af0[3], bf[0], bf[1]);
                    mma16816(acc[0][2 * ntp + 1], af0[0], af0[1], af0[2], af0[3], bf[2], bf[3]);
                    mma16816(acc[1][2 * ntp],     af1[0], af1[1], af1[2], af1[3], bf[0], bf[1]);
                    mma16816(acc[1][2 * ntp + 1], af1[0], af1[1], af1[2], af1[3], bf[2], bf[3]);
                }
            }
        } else {
            // A from registers (aPack), K=128 (8 ksteps)
#pragma unroll
            for (int ks = 0; ks < 8; ks++) {
#pragma unroll
                for (int ntp = 0; ntp < 8; ntp++) {
                    unsigned bf[4];
                    ldsm_x4(bf, bb + (ntp * 16 * SH) * 2 + ks * 32);
                    mma16816(acc[0][2 * ntp], aPack[0][2 * ks][0], aPack[0][2 * ks][1],
                             aPack[0][2 * ks + 1][0], aPack[0][2 * ks + 1][1], bf[0], bf[1]);
                    mma16816(acc[0][2 * ntp + 1], aPack[0][2 * ks][0], aPack[0][2 * ks][1],
                             aPack[0][2 * ks + 1][0], aPack[0][2 * ks + 1][1], bf[2], bf[3]);
                    mma16816(acc[1][2 * ntp], aPack[1][2 * ks][0], aPack[1][2 * ks][1],
                             aPack[1][2 * ks + 1][0], aPack[1][2 * ks + 1][1], bf[0], bf[1]);
                    mma16816(acc[1][2 * ntp + 1], aPack[1][2 * ks][0], aPack[1][2 * ks][1],
                             aPack[1][2 * ks + 1][0], aPack[1][2 * ks + 1][1], bf[2], bf[3]);
                }
            }
        }

        const float* lb = sbias + li * 128;
        if (layer < 3) {
            // bias + silu -> repack into aPack (registers only)
#pragma unroll
            for (int mt = 0; mt < 2; mt++)
#pragma unroll
                for (int nt = 0; nt < 16; nt++) {
                    int c = nt * 8 + tig * 2;
                    float b0v = lb[c], b1v = lb[c + 1];
                    float v0 = fast_silu(acc[mt][nt][0] + b0v);
                    float v1 = fast_silu(acc[mt][nt][1] + b1v);
                    float v2 = fast_silu(acc[mt][nt][2] + b0v);
                    float v3 = fast_silu(acc[mt][nt][3] + b1v);
                    aPack[mt][nt][0] = packh2(v0, v1);
                    aPack[mt][nt][1] = packh2(v2, v3);
                }
        } else {
            // fused final GEMV from registers: silu then dot with W2
            const float* w2 = w2s + (li >> 2) * 128;
            float* dst = (li >> 2) ? traw : sraw;
#pragma unroll
            for (int mt = 0; mt < 2; mt++) {
                float p0 = 0.f, p1 = 0.f;
#pragma unroll
                for (int nt = 0; nt < 16; nt++) {
                    int c = nt * 8 + tig * 2;
                    float b0v = lb[c], b1v = lb[c + 1];
                    float w0 = w2[c], w1 = w2[c + 1];
                    p0 += fast_silu(acc[mt][nt][0] + b0v) * w0
                        + fast_silu(acc[mt][nt][1] + b1v) * w1;
                    p1 += fast_silu(acc[mt][nt][2] + b0v) * w0
                        + fast_silu(acc[mt][nt][3] + b1v) * w1;
                }
                p0 += __shfl_xor_sync(0xffffffffu, p0, 1);
                p0 += __shfl_xor_sync(0xffffffffu, p0, 2);
                p1 += __shfl_xor_sync(0xffffffffu, p1, 1);
                p1 += __shfl_xor_sync(0xffffffffu, p1, 2);
                if (tig == 0) {
                    dst[wid * 32 + mt * 16 + gid]     = p0;
                    dst[wid * 32 + mt * 16 + gid + 8] = p1;
                }
            }
        }
    }
    __syncthreads();

    // ===== coupling epilogue + deterministic block reduce of s =====
    {
        int g0 = tile * TOKPC + tid;
        float zold = (PASS == 0) ? __ldg(&x[g0 * 2]) : __ldg(&x[g0 * 2 + 1]);
        float sv = tanhf(sraw[tid] + __ldg(&b2[PASS * 2])) * 1.5f;
        float tv = traw[tid] + __ldg(&b2[PASS * 2 + 1]);
        float z = zold * __expf(sv) + tv;
        out[g0 * 2 + PASS] = z;
        sred[tid] = sv;
    }
    __syncthreads();
    if (tid < 128) sred[tid] += sred[tid + 128];
    __syncthreads();
    if (tid < 64) sred[tid] += sred[tid + 64];
    __syncthreads();
    if (tid < 32) {
        float v = sred[tid] + sred[tid + 32];
#pragma unroll
        for (int off = 16; off; off >>= 1) v += __shfl_xor_sync(0xffffffffu, v, off);
        if (tid == 0) g_part[PASS][tile] = v;
    }
}

// ---------------- log-det reduce ----------------
__global__ void k_reduce(float* __restrict__ out) {
    int b = threadIdx.x;
    if (b < BB) {
        float acc = 0.f;
        for (int i = 0; i < 16; i++)
            acc += g_part[0][b * 16 + i] + g_part[1][b * 16 + i];
        out[(size_t)NTOK * 2 + b] = acc;
    }
}

// ---------------- launcher ----------------
extern "C" void kernel_launch(void* const* d_in, const int* in_sizes, int n_in,
                              void* d_out, int out_size) {
    const float* x    = (const float*)d_in[0];
    const float* w    = (const float*)d_in[1];
    const float* cond = (const float*)d_in[2];
    const float* W0   = (const float*)d_in[3];
    const float* b0   = (const float*)d_in[4];
    const float* W1   = (const float*)d_in[5];
    const float* b1   = (const float*)d_in[6];
    const float* W2   = (const float*)d_in[7];
    const float* b2   = (const float*)d_in[8];
    float* out = (float*)d_out;

    const int SMEM = 165888;
    cudaFuncSetAttribute(k_pass<0>, cudaFuncAttributeMaxDynamicSharedMemorySize, SMEM);
    cudaFuncSetAttribute(k_pass<1>, cudaFuncAttributeMaxDynamicSharedMemorySize, SMEM);

    k_transpose<<<4096, 256>>>(w);
    k_pack<<<1024, 256>>>(W0, b0, W1, b1);
    k_pass<0><<<NCTAS, 256, SMEM>>>(x, cond, W2, b2, out);
    k_pass<1><<<NCTAS, 256, SMEM>>>(x, cond, W2, b2, out);
    k_reduce<<<1, 64>>>(out);
}